// round 14
// baseline (speedup 1.0000x reference)
#include <cuda_runtime.h>
#include <cuda_bf16.h>

// BuzzLoss: B=8192 rows, T=1024 cols.
// Fine-grained persistent-stream variant: 64-thread CTAs (2 warps), one row
// per warp, grid 4096. 32 resident CTAs/SM turn over INDIVIDUALLY, so load
// bursts from fresh warps arrive continuously instead of in synchronized
// CTA-generation waves (the R7-R13 structure's remaining inefficiency).
// Per-warp math = proven R8 body: 16 coalesced LDG.128, segment reduction on
// arrival, 8 interleaved warp product-scans, 8-deep serial combine, warp
// reduce. Each warp fires one RED (fire-and-forget atomicAdd) into a
// __device__ partial; ticket-based last-CTA finalize (self-resetting,
// graph-replay safe). No zero-kernel.

#define FULL_MASK 0xFFFFFFFFu
#define ROWS_PER_CTA 2
#define THREADS 64

__device__ float g_partial = 0.0f;
__device__ unsigned int g_ticket = 0u;

__global__ __launch_bounds__(THREADS)
void buzz_loss_kernel(const float* __restrict__ conf,
                      const float* __restrict__ acc,
                      float* __restrict__ out,
                      float negInvB) {
    const int tid  = threadIdx.x;
    const int lane = tid & 31;
    const int wid  = tid >> 5;
    const size_t row = (size_t)blockIdx.x * ROWS_PER_CTA + wid;

    const float4* c4 = reinterpret_cast<const float4*>(conf + row * 1024) + lane;
    const float4* a4 = reinterpret_cast<const float4*>(acc  + row * 1024) + lane;

    // ---- Phase 1: 16 coalesced LDG.128 + per-segment reduction on arrival ----
    float p[8], s1loc[8], s2loc[8];
    float lastA = 0.0f;

    #pragma unroll
    for (int j = 0; j < 8; j++) {
        const float4 c = c4[j * 32];
        const float4 a = a4[j * 32];

        const float q0 = 1.0f - c.x;
        const float q1 = 1.0f - c.y;
        const float q2 = 1.0f - c.z;
        const float q3 = 1.0f - c.w;

        const float lb0 = c.x;
        const float lb1 = c.y * q0;
        const float lb2 = c.z * (q0 * q1);
        const float lb3 = c.w * (q0 * q1 * q2);

        p[j] = (q0 * q1) * (q2 * q3);
        s1loc[j] = fmaf(lb0, a.x, fmaf(lb1, a.y, fmaf(lb2, a.z, lb3 * a.w)));
        s2loc[j] = (lb0 + lb1) + (lb2 + lb3);

        if (j == 7) lastA = a.w;           // lane 31 -> acc[row, 1023]
    }

    // ---- Phase 2: 8 interleaved warp inclusive product-scans ----
    #pragma unroll
    for (int d = 1; d < 32; d <<= 1) {
        #pragma unroll
        for (int j = 0; j < 8; j++) {
            float v = __shfl_up_sync(FULL_MASK, p[j], d);
            if (lane >= d) p[j] *= v;
        }
    }

    float tot[8], E[8];
    #pragma unroll
    for (int j = 0; j < 8; j++) {
        tot[j] = __shfl_sync(FULL_MASK, p[j], 31);
        E[j]   = __shfl_up_sync(FULL_MASK, p[j], 1);
        if (lane == 0) E[j] = 1.0f;
    }

    // Serial cross-segment chain (8 deep)
    float R = 1.0f, s1 = 0.0f, s2 = 0.0f;
    #pragma unroll
    for (int j = 0; j < 8; j++) {
        const float Ej = E[j] * R;
        s1 = fmaf(Ej, s1loc[j], s1);
        s2 = fmaf(Ej, s2loc[j], s2);
        R *= tot[j];
    }

    // Warp reduce (two values)
    #pragma unroll
    for (int d = 16; d >= 1; d >>= 1) {
        s1 += __shfl_down_sync(FULL_MASK, s1, d);
        s2 += __shfl_down_sync(FULL_MASK, s2, d);
    }
    const float accLast = __shfl_sync(FULL_MASK, lastA, 31);

    if (lane == 0) {
        const float score = s1 + (1.0f - s2) * accLast;
        atomicAdd(&g_partial, score);      // result unused -> RED (no return)
    }

    __syncthreads();                       // both warps' REDs issued

    // ---- ticket-based last-CTA finalize (self-resetting, replay-safe) ----
    if (tid == 0) {
        __threadfence();
        const unsigned t = atomicAdd(&g_ticket, 1u);
        if (t == gridDim.x - 1) {
            const float total = atomicExch(&g_partial, 0.0f);
            atomicExch(&g_ticket, 0u);
            out[0] = total * negInvB;
        }
    }
}

extern "C" void kernel_launch(void* const* d_in, const int* in_sizes, int n_in,
                              void* d_out, int out_size) {
    const float* conf = (const float*)d_in[0];
    const float* acc  = (const float*)d_in[1];
    float* out = (float*)d_out;

    const int total = in_sizes[0];
    const int T = 1024;
    const int B = total / T;

    buzz_loss_kernel<<<B / ROWS_PER_CTA, THREADS>>>(conf, acc, out,
                                                    -1.0f / (float)B);
}

// round 15
// speedup vs baseline: 1.0481x; 1.0481x over previous
#include <cuda_runtime.h>
#include <cuda_bf16.h>

// BuzzLoss: B=8192 rows, T=1024 cols.
// Final form = R7 (best measured) + validated micro-trims:
//  - ONE WARP PER ROW, 8 rows per 256-thread CTA, grid 1024.
//  - 16 coalesced LDG.128 front-batched (c[8] then a[8]).
//  - 8 interleaved warp product-scans; 8-deep serial cross-segment combine.
//  - accLast folded BEFORE the reduce -> single-value warp reduce (5 shfls).
//  - No smem, no CTA barriers: each warp fires one fire-and-forget atomicAdd
//    (8192 single-address REDs, ~0.854 cyc/op -- negligible).
//  - Separate 1-thread zero kernel (measured faster than ticket finalize).

#define FULL_MASK 0xFFFFFFFFu
#define ROWS_PER_CTA 8

__global__ void buzz_zero_kernel(float* out) {
    out[0] = 0.0f;
}

__global__ __launch_bounds__(256)
void buzz_loss_kernel(const float* __restrict__ conf,
                      const float* __restrict__ acc,
                      float* __restrict__ out,
                      float negInvB) {
    const int tid  = threadIdx.x;
    const int lane = tid & 31;
    const int wid  = tid >> 5;
    const size_t row = (size_t)blockIdx.x * ROWS_PER_CTA + wid;

    const float4* c4 = reinterpret_cast<const float4*>(conf + row * 1024) + lane;
    const float4* a4 = reinterpret_cast<const float4*>(acc  + row * 1024) + lane;

    // ---- Front-batched loads: 16 independent coalesced LDG.128 ----
    float4 c[8], a[8];
    #pragma unroll
    for (int j = 0; j < 8; j++) c[j] = c4[j * 32];
    #pragma unroll
    for (int j = 0; j < 8; j++) a[j] = a4[j * 32];

    // ---- Per-segment local products ----
    float inc[8];
    #pragma unroll
    for (int j = 0; j < 8; j++) {
        inc[j] = (1.0f - c[j].x) * (1.0f - c[j].y) *
                 (1.0f - c[j].z) * (1.0f - c[j].w);
    }

    // ---- 8 interleaved warp inclusive product-scans ----
    #pragma unroll
    for (int d = 1; d < 32; d <<= 1) {
        #pragma unroll
        for (int j = 0; j < 8; j++) {
            float v = __shfl_up_sync(FULL_MASK, inc[j], d);
            if (lane >= d) inc[j] *= v;
        }
    }

    // ---- Serial cross-segment combine (8 deep) ----
    float R = 1.0f, s1 = 0.0f, s2 = 0.0f;
    #pragma unroll
    for (int j = 0; j < 8; j++) {
        const float total = __shfl_sync(FULL_MASK, inc[j], 31);
        float E = __shfl_up_sync(FULL_MASK, inc[j], 1);
        if (lane == 0) E = 1.0f;
        E *= R;

        const float q0 = 1.0f - c[j].x;
        const float q1 = 1.0f - c[j].y;
        const float q2 = 1.0f - c[j].z;

        const float b0 = c[j].x * E;
        const float b1 = c[j].y * (E * q0);
        const float b2 = c[j].z * (E * q0 * q1);
        const float b3 = c[j].w * (E * q0 * q1 * q2);

        s1 = fmaf(b0, a[j].x, fmaf(b1, a[j].y,
             fmaf(b2, a[j].z, fmaf(b3, a[j].w, s1))));
        s2 += (b0 + b1) + (b2 + b3);

        R *= total;
    }

    // ---- Fold accLast, then single-value warp reduce (5 shfls) ----
    const float accLast = __shfl_sync(FULL_MASK, a[7].w, 31);
    float contrib = fmaf(-accLast, s2, s1);
    if (lane == 31) contrib += accLast;

    #pragma unroll
    for (int d = 16; d >= 1; d >>= 1) {
        contrib += __shfl_down_sync(FULL_MASK, contrib, d);
    }

    if (lane == 0) {
        atomicAdd(out, contrib * negInvB);   // fire-and-forget RED
    }
}

extern "C" void kernel_launch(void* const* d_in, const int* in_sizes, int n_in,
                              void* d_out, int out_size) {
    const float* conf = (const float*)d_in[0];
    const float* acc  = (const float*)d_in[1];
    float* out = (float*)d_out;

    const int total = in_sizes[0];
    const int T = 1024;
    const int B = total / T;

    buzz_zero_kernel<<<1, 1>>>(out);
    buzz_loss_kernel<<<B / ROWS_PER_CTA, 256>>>(conf, acc, out,
                                                -1.0f / (float)B);
}

// round 16
// speedup vs baseline: 1.9432x; 1.8541x over previous
#include <cuda_runtime.h>
#include <cuda_bf16.h>

// BuzzLoss: B=8192 rows, T=1024 cols.
// R7 (best measured, 10.7us) with three non-structural trims:
//  - 16 front-batched coalesced LDG.128 issued FIRST; the (tiny) smem init +
//    __syncthreads sits after load issue, overlapping load latency.
//  - accLast folded before the reduce -> single-value warp reduce (5 shfls).
//  - per-warp smem store + warp-0 reduce -> exactly ONE global atomic per CTA
//    (1024 total; the R14/R15 lesson: >1024 same-address REDs serialize).

#define FULL_MASK 0xFFFFFFFFu
#define ROWS_PER_CTA 8

__global__ void buzz_zero_kernel(float* out) {
    out[0] = 0.0f;
}

__global__ __launch_bounds__(256)
void buzz_loss_kernel(const float* __restrict__ conf,
                      const float* __restrict__ acc,
                      float* __restrict__ out,
                      float negInvB) {
    const int tid  = threadIdx.x;
    const int lane = tid & 31;
    const int wid  = tid >> 5;
    const size_t row = (size_t)blockIdx.x * ROWS_PER_CTA + wid;

    __shared__ float s_score[ROWS_PER_CTA];

    const float4* c4 = reinterpret_cast<const float4*>(conf + row * 1024) + lane;
    const float4* a4 = reinterpret_cast<const float4*>(acc  + row * 1024) + lane;

    // ---- Front-batched loads: 16 independent coalesced LDG.128 ----
    float4 c[8], a[8];
    #pragma unroll
    for (int j = 0; j < 8; j++) c[j] = c4[j * 32];
    #pragma unroll
    for (int j = 0; j < 8; j++) a[j] = a4[j * 32];

    // ---- Per-segment local products (first consumption of c) ----
    float inc[8];
    #pragma unroll
    for (int j = 0; j < 8; j++) {
        inc[j] = (1.0f - c[j].x) * (1.0f - c[j].y) *
                 (1.0f - c[j].z) * (1.0f - c[j].w);
    }

    // ---- 8 interleaved warp inclusive product-scans ----
    #pragma unroll
    for (int d = 1; d < 32; d <<= 1) {
        #pragma unroll
        for (int j = 0; j < 8; j++) {
            float v = __shfl_up_sync(FULL_MASK, inc[j], d);
            if (lane >= d) inc[j] *= v;
        }
    }

    // ---- Serial cross-segment combine (8 deep) ----
    float R = 1.0f, s1 = 0.0f, s2 = 0.0f;
    #pragma unroll
    for (int j = 0; j < 8; j++) {
        const float total = __shfl_sync(FULL_MASK, inc[j], 31);
        float E = __shfl_up_sync(FULL_MASK, inc[j], 1);
        if (lane == 0) E = 1.0f;
        E *= R;

        const float q0 = 1.0f - c[j].x;
        const float q1 = 1.0f - c[j].y;
        const float q2 = 1.0f - c[j].z;

        const float b0 = c[j].x * E;
        const float b1 = c[j].y * (E * q0);
        const float b2 = c[j].z * (E * q0 * q1);
        const float b3 = c[j].w * (E * q0 * q1 * q2);

        s1 = fmaf(b0, a[j].x, fmaf(b1, a[j].y,
             fmaf(b2, a[j].z, fmaf(b3, a[j].w, s1))));
        s2 += (b0 + b1) + (b2 + b3);

        R *= total;
    }

    // ---- Fold accLast, single-value warp reduce (5 shfls) ----
    const float accLast = __shfl_sync(FULL_MASK, a[7].w, 31);
    float contrib = fmaf(-accLast, s2, s1);
    if (lane == 31) contrib += accLast;

    #pragma unroll
    for (int d = 16; d >= 1; d >>= 1) {
        contrib += __shfl_down_sync(FULL_MASK, contrib, d);
    }

    if (lane == 0) s_score[wid] = contrib;
    __syncthreads();

    // ---- Warp 0: reduce 8 row scores, ONE global atomic per CTA ----
    if (wid == 0) {
        float t = (lane < ROWS_PER_CTA) ? s_score[lane] : 0.0f;
        #pragma unroll
        for (int d = 4; d >= 1; d >>= 1) {
            t += __shfl_down_sync(FULL_MASK, t, d);
        }
        if (lane == 0) {
            atomicAdd(out, t * negInvB);
        }
    }
}

extern "C" void kernel_launch(void* const* d_in, const int* in_sizes, int n_in,
                              void* d_out, int out_size) {
    const float* conf = (const float*)d_in[0];
    const float* acc  = (const float*)d_in[1];
    float* out = (float*)d_out;

    const int total = in_sizes[0];
    const int T = 1024;
    const int B = total / T;

    buzz_zero_kernel<<<1, 1>>>(out);
    buzz_loss_kernel<<<B / ROWS_PER_CTA, 256>>>(conf, acc, out,
                                                -1.0f / (float)B);
}